// round 1
// baseline (speedup 1.0000x reference)
#include <cuda_runtime.h>
#include <math.h>

#define T_IN  2048
#define F_DIM 256
#define H_DIM 384
#define TP    2051            // T_IN + 3 (conv output length)
#define INV_SQRT_H 0.05103103703f   // 1/sqrt(384)

// ---------------- scratch (static device globals; no allocations) ----------
__device__ float g_xp[TP * F_DIM];        // (t, f)  conv output
__device__ float g_k [H_DIM * TP];        // (b, t)  scaled k
__device__ float g_v [H_DIM * TP];        // (b, t)
__device__ float g_zi[H_DIM * TP];        // (b, t)  raw input-gate preact
__device__ float g_lf[H_DIM * TP];        // (b, t)  log sigmoid(forget preact)
__device__ float g_contrib[H_DIM * TP];   // (b, t)  exp(zi+S)*k*qT[b]
__device__ float g_wp[6 * TP];            // partial reductions over b-groups
__device__ float g_w [TP];                // w_t
__device__ float g_qT[H_DIM];             // raw q at last step
__device__ float g_oT[H_DIM];             // sigmoid(o) at last step

// ---------------- 1. causal-ish conv (kernel=4, pad (3,3)) -----------------
__global__ void conv_kernel(const float* __restrict__ x,
                            const float* __restrict__ cw,
                            const float* __restrict__ cb) {
    int idx = blockIdx.x * blockDim.x + threadIdx.x;
    if (idx >= TP * F_DIM) return;
    int t = idx / F_DIM, f = idx % F_DIM;
    float acc = cb[0];
#pragma unroll
    for (int j = 0; j < 4; ++j) {
        int s = t + j - 3;
        if (s >= 0 && s < T_IN) acc = fmaf(cw[j], x[s * F_DIM + f], acc);
    }
    g_xp[idx] = acc;
}

// ---------------- 2. q_T and sigmoid(o_T) from last xp row -----------------
__global__ void qo_kernel(const float* __restrict__ Wq, const float* __restrict__ bq,
                          const float* __restrict__ Wo, const float* __restrict__ bo) {
    int warp = threadIdx.x >> 5, lane = threadIdx.x & 31;
    int b = blockIdx.x * 8 + warp;
    if (b >= H_DIM) return;
    const float* W  = blockIdx.y ? Wo : Wq;
    const float* bb = blockIdx.y ? bo : bq;
    const float* xr = &g_xp[(TP - 1) * F_DIM];
    float s = 0.f;
    for (int f = lane; f < F_DIM; f += 32) s = fmaf(W[b * F_DIM + f], xr[f], s);
#pragma unroll
    for (int off = 16; off; off >>= 1) s += __shfl_xor_sync(0xffffffffu, s, off);
    if (lane == 0) {
        float z = s + bb[b];
        if (blockIdx.y) g_oT[b] = 1.f / (1.f + expf(-z));
        else            g_qT[b] = z;
    }
}

// ---------------- 3. tiled GEMM: xp(2051x256) @ W^T(256x384) for k,v,i,f ---
#define BM 64
#define BN 64
#define BK 16
__global__ __launch_bounds__(256)
void proj_gemm(const float* __restrict__ Wk, const float* __restrict__ bk,
               const float* __restrict__ Wv, const float* __restrict__ bv,
               const float* __restrict__ Wi, const float* __restrict__ bi,
               const float* __restrict__ Wf, const float* __restrict__ bf) {
    __shared__ float As[BK][BM + 1];
    __shared__ float Bs[BK][BN + 1];
    int proj = blockIdx.z;
    const float* W; const float* bias; float* out;
    switch (proj) {
        case 0: W = Wk; bias = bk; out = g_k;  break;
        case 1: W = Wv; bias = bv; out = g_v;  break;
        case 2: W = Wi; bias = bi; out = g_zi; break;
        default:W = Wf; bias = bf; out = g_lf; break;
    }
    int t0 = blockIdx.x * BM;
    int n0 = blockIdx.y * BN;
    int tid = threadIdx.x;
    int tn = tid & 15, tm = tid >> 4;

    float acc[4][4] = {};
    for (int k0 = 0; k0 < F_DIM; k0 += BK) {
#pragma unroll
        for (int i = 0; i < 4; ++i) {
            int idx = tid + i * 256;
            int m = idx >> 4, kk = idx & 15;
            int tt = t0 + m;
            As[kk][m] = (tt < TP) ? g_xp[tt * F_DIM + k0 + kk] : 0.f;
            Bs[kk][m] = W[(n0 + m) * F_DIM + k0 + kk];
        }
        __syncthreads();
#pragma unroll
        for (int kk = 0; kk < BK; ++kk) {
            float a[4], b[4];
#pragma unroll
            for (int i = 0; i < 4; ++i) a[i] = As[kk][tm * 4 + i];
#pragma unroll
            for (int j = 0; j < 4; ++j) b[j] = Bs[kk][tn * 4 + j];
#pragma unroll
            for (int i = 0; i < 4; ++i)
#pragma unroll
                for (int j = 0; j < 4; ++j)
                    acc[i][j] = fmaf(a[i], b[j], acc[i][j]);
        }
        __syncthreads();
    }

#pragma unroll
    for (int j = 0; j < 4; ++j) {
        int n = n0 + tn * 4 + j;
        float bias_n = bias[n];
#pragma unroll
        for (int i = 0; i < 4; ++i) {
            int t = t0 + tm * 4 + i;
            if (t >= TP) continue;
            float z = acc[i][j] + bias_n;
            float val;
            if (proj == 0)      val = z * INV_SQRT_H;                      // k scaled
            else if (proj == 3) val = fminf(z, 0.f) - log1pf(expf(-fabsf(z))); // log sigmoid
            else                val = z;                                   // v raw, zi raw
            out[n * TP + t] = val;
        }
    }
}

// ---------------- 4. per-channel suffix scan of log f; contributions -------
__global__ __launch_bounds__(256)
void scan_kernel() {
    const int b = blockIdx.x;
    const int tid = threadIdx.x;
    const int CH = 9;                       // ceil(2051/256)
    const float* lf = &g_lf[b * TP];
    const float* zi = &g_zi[b * TP];
    const float* kk = &g_k [b * TP];
    const float qb  = g_qT[b];
    float* co = &g_contrib[b * TP];

    int lo = tid * CH;
    int hi = min(lo + CH, TP);

    float s = 0.f;
    for (int t = lo; t < hi; ++t) s += lf[t];

    __shared__ float sfx[256];
    sfx[tid] = s;
    __syncthreads();
    // inclusive suffix scan (Hillis-Steele)
#pragma unroll
    for (int d = 1; d < 256; d <<= 1) {
        float add = (tid + d < 256) ? sfx[tid + d] : 0.f;
        __syncthreads();
        sfx[tid] += add;
        __syncthreads();
    }
    float run = (tid + 1 < 256) ? sfx[tid + 1] : 0.f;  // sum over later chunks
    for (int t = hi - 1; t >= lo; --t) {
        // S(t) = sum_{s>t} log f_s   ->  g_t = exp(zi_t + S) ; contrib = g*k*q
        co[t] = expf(zi[t] + run) * kk[t] * qb;
        run += lf[t];
    }
}

// ---------------- 5. reduce contrib over b (6 partial groups of 64) --------
__global__ void reduce_w() {
    int t = blockIdx.x * blockDim.x + threadIdx.x;
    if (t >= TP) return;
    int y = blockIdx.y;
    const float* base = &g_contrib[(size_t)y * 64 * TP];
    float s = 0.f;
#pragma unroll 8
    for (int b = 0; b < 64; ++b) s += base[b * TP + t];
    g_wp[y * TP + t] = s;
}

// ---------------- 6. combine partials into w ------------------------------
__global__ void combine_w() {
    int t = blockIdx.x * blockDim.x + threadIdx.x;
    if (t >= TP) return;
    float s = 0.f;
#pragma unroll
    for (int y = 0; y < 6; ++y) s += g_wp[y * TP + t];
    g_w[t] = s;
}

// ---------------- 7. final: h[a] = o[a] * (v_a . w) / max(|sum w|,1) -------
__global__ __launch_bounds__(256)
void final_kernel(float* __restrict__ out) {
    const int a = blockIdx.x;
    const int tid = threadIdx.x;
    const float* v = &g_v[a * TP];
    float num = 0.f, den = 0.f;
    for (int t = tid; t < TP; t += 256) {
        float wt = g_w[t];
        num = fmaf(v[t], wt, num);
        den += wt;
    }
    __shared__ float sn[256], sd[256];
    sn[tid] = num; sd[tid] = den;
    __syncthreads();
#pragma unroll
    for (int s = 128; s; s >>= 1) {
        if (tid < s) { sn[tid] += sn[tid + s]; sd[tid] += sd[tid + s]; }
        __syncthreads();
    }
    if (tid == 0) {
        float dd = fmaxf(fabsf(sd[0]), 1.0f);
        out[a] = g_oT[a] * sn[0] / dd;
    }
}

// ---------------------------------------------------------------------------
extern "C" void kernel_launch(void* const* d_in, const int* in_sizes, int n_in,
                              void* d_out, int out_size) {
    const float* x  = (const float*)d_in[0];
    const float* Wq = (const float*)d_in[1];  const float* bq = (const float*)d_in[2];
    const float* Wk = (const float*)d_in[3];  const float* bk = (const float*)d_in[4];
    const float* Wv = (const float*)d_in[5];  const float* bv = (const float*)d_in[6];
    const float* Wi = (const float*)d_in[7];  const float* bi = (const float*)d_in[8];
    const float* Wf = (const float*)d_in[9];  const float* bf = (const float*)d_in[10];
    const float* Wo = (const float*)d_in[11]; const float* bo = (const float*)d_in[12];
    const float* cw = (const float*)d_in[13]; const float* cb = (const float*)d_in[14];
    float* out = (float*)d_out;

    conv_kernel<<<(TP * F_DIM + 255) / 256, 256>>>(x, cw, cb);
    qo_kernel<<<dim3(48, 2), 256>>>(Wq, bq, Wo, bo);
    proj_gemm<<<dim3((TP + BM - 1) / BM, H_DIM / BN, 4), 256>>>(Wk, bk, Wv, bv,
                                                                Wi, bi, Wf, bf);
    scan_kernel<<<H_DIM, 256>>>();
    reduce_w<<<dim3((TP + 255) / 256, 6), 256>>>();
    combine_w<<<(TP + 255) / 256, 256>>>();
    final_kernel<<<H_DIM, 256>>>(out);
}

// round 2
// speedup vs baseline: 1.3503x; 1.3503x over previous
#include <cuda_runtime.h>
#include <math.h>

#define T_IN  2048
#define F_DIM 256
#define H_DIM 384
#define TP    2051            // T_IN + 3 (conv output length)
#define TPAD  2056            // padded row stride (16B-aligned: 2056*4 % 16 == 0)
#define INV_SQRT_H 0.05103103703f   // 1/sqrt(384)

typedef unsigned long long ull;

// ---------------- scratch (static device globals; no allocations) ----------
__device__ __align__(16) float g_xp[TP * F_DIM];        // (t, f)  conv output
__device__ __align__(16) float g_k [H_DIM * TPAD];      // (b, t)  scaled k
__device__ __align__(16) float g_v [H_DIM * TPAD];      // (b, t)
__device__ __align__(16) float g_zi[H_DIM * TPAD];      // (b, t)  raw input-gate preact
__device__ __align__(16) float g_lf[H_DIM * TPAD];      // (b, t)  log sigmoid(forget)
__device__ __align__(16) float g_contrib[H_DIM * TPAD]; // (b, t)  exp(zi+S)*k*qT[b]
__device__ __align__(16) float g_w [TPAD];              // w_t
__device__ float g_qT[H_DIM];             // raw q at last step
__device__ float g_oT[H_DIM];             // sigmoid(o) at last step

// ---------------- packed f32x2 helpers -------------------------------------
__device__ __forceinline__ ull pack2(float x) {
    ull r; unsigned u = __float_as_uint(x);
    asm("mov.b64 %0, {%1, %1};" : "=l"(r) : "r"(u));
    return r;
}
__device__ __forceinline__ void fma2(ull& d, ull a, ull b) {
    asm("fma.rn.f32x2 %0, %1, %2, %0;" : "+l"(d) : "l"(a), "l"(b));
}
__device__ __forceinline__ void unpack2(ull p, float& lo, float& hi) {
    unsigned a, b;
    asm("mov.b64 {%0, %1}, %2;" : "=r"(a), "=r"(b) : "l"(p));
    lo = __uint_as_float(a); hi = __uint_as_float(b);
}

// ---------------- 1. conv (kernel=4, pad (3,3)) -----------------------------
__global__ void conv_kernel(const float* __restrict__ x,
                            const float* __restrict__ cw,
                            const float* __restrict__ cb) {
    int idx = blockIdx.x * blockDim.x + threadIdx.x;
    if (idx >= TP * F_DIM) return;
    int t = idx / F_DIM, f = idx % F_DIM;
    float acc = cb[0];
#pragma unroll
    for (int j = 0; j < 4; ++j) {
        int s = t + j - 3;
        if (s >= 0 && s < T_IN) acc = fmaf(cw[j], x[s * F_DIM + f], acc);
    }
    g_xp[idx] = acc;
}

// ---------------- 2. q_T and sigmoid(o_T) from last xp row ------------------
__global__ void qo_kernel(const float* __restrict__ Wq, const float* __restrict__ bq,
                          const float* __restrict__ Wo, const float* __restrict__ bo) {
    int warp = threadIdx.x >> 5, lane = threadIdx.x & 31;
    int b = blockIdx.x * 8 + warp;
    if (b >= H_DIM) return;
    const float* W  = blockIdx.y ? Wo : Wq;
    const float* bb = blockIdx.y ? bo : bq;
    const float* xr = &g_xp[(TP - 1) * F_DIM];
    float s = 0.f;
    for (int f = lane; f < F_DIM; f += 32) s = fmaf(W[b * F_DIM + f], xr[f], s);
#pragma unroll
    for (int off = 16; off; off >>= 1) s += __shfl_xor_sync(0xffffffffu, s, off);
    if (lane == 0) {
        float z = s + bb[b];
        if (blockIdx.y) g_oT[b] = 1.f / (1.f + expf(-z));
        else            g_qT[b] = z;
    }
}

// ---------------- 3. f32x2 GEMM: xp(2051x256) @ W^T for k,v,i,f -------------
#define BM 128
#define BN 64
#define BK 16
#define AS_S (BM + 2)   // 130: 8B-aligned row stride
#define BS_S (BN + 4)   // 68: 16B-aligned row stride

__global__ __launch_bounds__(256, 2)
void proj_gemm(const float* __restrict__ Wk, const float* __restrict__ bk,
               const float* __restrict__ Wv, const float* __restrict__ bv,
               const float* __restrict__ Wi, const float* __restrict__ bi,
               const float* __restrict__ Wf, const float* __restrict__ bf) {
    __shared__ float As[BK][AS_S];
    __shared__ float Bs[BK][BS_S];

    const int proj = blockIdx.y / 6;           // 0..3
    const int n0   = (blockIdx.y % 6) * BN;
    const int t0   = blockIdx.x * BM;
    const int tid  = threadIdx.x;
    const int tn   = tid & 15;                  // 16 col groups of 4
    const int tm   = tid >> 4;                  // 16 row groups of 8

    const float* W; const float* bias; float* out;
    switch (proj) {
        case 0: W = Wk; bias = bk; out = g_k;  break;
        case 1: W = Wv; bias = bv; out = g_v;  break;
        case 2: W = Wi; bias = bi; out = g_zi; break;
        default:W = Wf; bias = bf; out = g_lf; break;
    }

    ull acc[4][4];
#pragma unroll
    for (int i = 0; i < 4; ++i)
#pragma unroll
        for (int j = 0; j < 4; ++j) acc[i][j] = 0ull;

    for (int k0 = 0; k0 < F_DIM; k0 += BK) {
        // Load A tile: 128 rows x 16 k as float4 (q = idx&3 selects 4-float chunk)
#pragma unroll
        for (int i = 0; i < 2; ++i) {
            int idx = tid + i * 256;            // 0..511
            int row = idx >> 2, q = idx & 3;
            int tt = t0 + row;
            float4 val = make_float4(0.f, 0.f, 0.f, 0.f);
            if (tt < TP)
                val = *reinterpret_cast<const float4*>(&g_xp[tt * F_DIM + k0 + q * 4]);
            As[q * 4 + 0][row] = val.x;
            As[q * 4 + 1][row] = val.y;
            As[q * 4 + 2][row] = val.z;
            As[q * 4 + 3][row] = val.w;
        }
        // Load B tile: 64 rows x 16 k
        {
            int row = tid >> 2, q = tid & 3;
            float4 val = *reinterpret_cast<const float4*>(&W[(n0 + row) * F_DIM + k0 + q * 4]);
            Bs[q * 4 + 0][row] = val.x;
            Bs[q * 4 + 1][row] = val.y;
            Bs[q * 4 + 2][row] = val.z;
            Bs[q * 4 + 3][row] = val.w;
        }
        __syncthreads();

#pragma unroll
        for (int kk = 0; kk < BK; ++kk) {
            const ull* a8 = reinterpret_cast<const ull*>(&As[kk][tm * 8]);
            ull a0 = a8[0], a1 = a8[1], a2v = a8[2], a3 = a8[3];
            float4 bv4 = *reinterpret_cast<const float4*>(&Bs[kk][tn * 4]);
            ull b0 = pack2(bv4.x), b1 = pack2(bv4.y), b2v = pack2(bv4.z), b3 = pack2(bv4.w);
            fma2(acc[0][0], a0, b0); fma2(acc[0][1], a0, b1);
            fma2(acc[0][2], a0, b2v); fma2(acc[0][3], a0, b3);
            fma2(acc[1][0], a1, b0); fma2(acc[1][1], a1, b1);
            fma2(acc[1][2], a1, b2v); fma2(acc[1][3], a1, b3);
            fma2(acc[2][0], a2v, b0); fma2(acc[2][1], a2v, b1);
            fma2(acc[2][2], a2v, b2v); fma2(acc[2][3], a2v, b3);
            fma2(acc[3][0], a3, b0); fma2(acc[3][1], a3, b1);
            fma2(acc[3][2], a3, b2v); fma2(acc[3][3], a3, b3);
        }
        __syncthreads();
    }

    // Epilogue: per column n, 8 contiguous t values -> 2x float4 stores
    const int tbase = t0 + tm * 8;
#pragma unroll
    for (int n = 0; n < 4; ++n) {
        int col = n0 + tn * 4 + n;
        float bias_n = bias[col];
        float vals[8];
#pragma unroll
        for (int mp = 0; mp < 4; ++mp)
            unpack2(acc[mp][n], vals[2 * mp], vals[2 * mp + 1]);
#pragma unroll
        for (int e = 0; e < 8; ++e) {
            float z = vals[e] + bias_n;
            if (proj == 0)      vals[e] = z * INV_SQRT_H;
            else if (proj == 3) vals[e] = fminf(z, 0.f) - log1pf(__expf(-fabsf(z)));
            else                vals[e] = z;
        }
        float* op = out + (size_t)col * TPAD + tbase;
        if (tbase + 7 < TP) {
            *reinterpret_cast<float4*>(op)     = make_float4(vals[0], vals[1], vals[2], vals[3]);
            *reinterpret_cast<float4*>(op + 4) = make_float4(vals[4], vals[5], vals[6], vals[7]);
        } else {
#pragma unroll
            for (int e = 0; e < 8; ++e)
                if (tbase + e < TP) op[e] = vals[e];
        }
    }
}

// ---------------- 4. per-channel suffix scan of log f; contributions --------
__global__ __launch_bounds__(256)
void scan_kernel() {
    const int b = blockIdx.x;
    const int tid = threadIdx.x;
    const int CH = 9;                       // ceil(2051/256)
    const float* lf = &g_lf[b * TPAD];
    const float* zi = &g_zi[b * TPAD];
    const float* kk = &g_k [b * TPAD];
    const float qb  = g_qT[b];
    float* co = &g_contrib[b * TPAD];

    int lo = tid * CH;
    int hi = min(lo + CH, TP);

    float s = 0.f;
    for (int t = lo; t < hi; ++t) s += lf[t];

    __shared__ float sfx[256];
    sfx[tid] = s;
    __syncthreads();
#pragma unroll
    for (int d = 1; d < 256; d <<= 1) {
        float add = (tid + d < 256) ? sfx[tid + d] : 0.f;
        __syncthreads();
        sfx[tid] += add;
        __syncthreads();
    }
    float run = (tid + 1 < 256) ? sfx[tid + 1] : 0.f;  // sum over later chunks
    for (int t = hi - 1; t >= lo; --t) {
        co[t] = __expf(zi[t] + run) * kk[t] * qb;
        run += lf[t];
    }
}

// ---------------- 5. fused reduce over b -> w --------------------------------
__global__ void reduce_w_fused() {
    int t = blockIdx.x * blockDim.x + threadIdx.x;
    if (t >= TP) return;
    float s = 0.f;
#pragma unroll 8
    for (int b = 0; b < H_DIM; ++b) s += g_contrib[b * TPAD + t];
    g_w[t] = s;
}

// ---------------- 6. final: h[a] = o[a] * (v_a . w) / max(|sum w|,1) ---------
__global__ __launch_bounds__(256)
void final_kernel(float* __restrict__ out) {
    const int a = blockIdx.x;
    const int tid = threadIdx.x;
    const float4* v4 = reinterpret_cast<const float4*>(&g_v[a * TPAD]);
    const float4* w4 = reinterpret_cast<const float4*>(g_w);
    float num = 0.f, den = 0.f;
    const int NV = TP / 4;                 // 512 full float4 -> elements [0,2048)
    for (int i = tid; i < NV; i += 256) {
        float4 v = v4[i], w = w4[i];
        num = fmaf(v.x, w.x, num); den += w.x;
        num = fmaf(v.y, w.y, num); den += w.y;
        num = fmaf(v.z, w.z, num); den += w.z;
        num = fmaf(v.w, w.w, num); den += w.w;
    }
    if (tid < TP - NV * 4) {               // tail elements 2048..2050
        int t = NV * 4 + tid;
        float wt = g_w[t];
        num = fmaf(g_v[a * TPAD + t], wt, num);
        den += wt;
    }
    __shared__ float sn[256], sd[256];
    sn[tid] = num; sd[tid] = den;
    __syncthreads();
#pragma unroll
    for (int s = 128; s; s >>= 1) {
        if (tid < s) { sn[tid] += sn[tid + s]; sd[tid] += sd[tid + s]; }
        __syncthreads();
    }
    if (tid == 0) {
        float dd = fmaxf(fabsf(sd[0]), 1.0f);
        out[a] = g_oT[a] * sn[0] / dd;
    }
}

// -----------------------------------------------------------------------------
extern "C" void kernel_launch(void* const* d_in, const int* in_sizes, int n_in,
                              void* d_out, int out_size) {
    const float* x  = (const float*)d_in[0];
    const float* Wq = (const float*)d_in[1];  const float* bq = (const float*)d_in[2];
    const float* Wk = (const float*)d_in[3];  const float* bk = (const float*)d_in[4];
    const float* Wv = (const float*)d_in[5];  const float* bv = (const float*)d_in[6];
    const float* Wi = (const float*)d_in[7];  const float* bi = (const float*)d_in[8];
    const float* Wf = (const float*)d_in[9];  const float* bf = (const float*)d_in[10];
    const float* Wo = (const float*)d_in[11]; const float* bo = (const float*)d_in[12];
    const float* cw = (const float*)d_in[13]; const float* cb = (const float*)d_in[14];
    float* out = (float*)d_out;

    conv_kernel<<<(TP * F_DIM + 255) / 256, 256>>>(x, cw, cb);
    qo_kernel<<<dim3(48, 2), 256>>>(Wq, bq, Wo, bo);
    proj_gemm<<<dim3((TP + BM - 1) / BM, 24), 256>>>(Wk, bk, Wv, bv, Wi, bi, Wf, bf);
    scan_kernel<<<H_DIM, 256>>>();
    reduce_w_fused<<<(TP + 255) / 256, 256>>>();
    final_kernel<<<H_DIM, 256>>>(out);
}

// round 3
// speedup vs baseline: 1.4546x; 1.0773x over previous
#include <cuda_runtime.h>
#include <math.h>

#define T_IN  2048
#define F_DIM 256
#define H_DIM 384
#define TP    2051            // T_IN + 3 (conv output length)
#define TPAD  2056            // padded row stride (16B-aligned)
#define INV_SQRT_H 0.05103103703f   // 1/sqrt(384)

typedef unsigned long long ull;

// ---------------- scratch (static device globals; no allocations) ----------
__device__ __align__(16) float g_xp[TP * F_DIM];        // (t, f)  conv output
__device__ __align__(16) float g_k [H_DIM * TPAD];      // (b, t)  scaled k
__device__ __align__(16) float g_v [H_DIM * TPAD];      // (b, t)
__device__ __align__(16) float g_zi[H_DIM * TPAD];      // (b, t)  input-gate preact
__device__ __align__(16) float g_lf[H_DIM * TPAD];      // (b, t)  log sigmoid(forget)
__device__ __align__(16) float g_contrib[H_DIM * TPAD]; // (b, t)
__device__ __align__(16) float g_w [TPAD];              // w_t
__device__ float g_qT[H_DIM];
__device__ float g_oT[H_DIM];
__device__ int   g_tmin;                  // first "live" timestep (global over b)

// ---------------- packed f32x2 helpers -------------------------------------
__device__ __forceinline__ ull pack2(float x) {
    ull r; unsigned u = __float_as_uint(x);
    asm("mov.b64 %0, {%1, %1};" : "=l"(r) : "r"(u));
    return r;
}
__device__ __forceinline__ void fma2(ull& d, ull a, ull b) {
    asm("fma.rn.f32x2 %0, %1, %2, %0;" : "+l"(d) : "l"(a), "l"(b));
}
__device__ __forceinline__ void unpack2(ull p, float& lo, float& hi) {
    unsigned a, b;
    asm("mov.b64 {%0, %1}, %2;" : "=r"(a), "=r"(b) : "l"(p));
    lo = __uint_as_float(a); hi = __uint_as_float(b);
}

// ---------------- 1. conv (kernel=4, pad (3,3)), float4 over features -------
__global__ void conv_kernel(const float* __restrict__ x,
                            const float* __restrict__ cw,
                            const float* __restrict__ cb) {
    int idx = blockIdx.x * blockDim.x + threadIdx.x;   // TP * 64 quads
    if (idx == 0) g_tmin = TP;                         // reset live bound
    if (idx >= TP * (F_DIM / 4)) return;
    int t = idx >> 6, qf = idx & 63;
    float b0 = cb[0];
    float4 acc = make_float4(b0, b0, b0, b0);
#pragma unroll
    for (int j = 0; j < 4; ++j) {
        int s = t + j - 3;
        if (s >= 0 && s < T_IN) {
            float4 xv = *reinterpret_cast<const float4*>(&x[s * F_DIM + qf * 4]);
            float w = cw[j];
            acc.x = fmaf(w, xv.x, acc.x);
            acc.y = fmaf(w, xv.y, acc.y);
            acc.z = fmaf(w, xv.z, acc.z);
            acc.w = fmaf(w, xv.w, acc.w);
        }
    }
    *reinterpret_cast<float4*>(&g_xp[t * F_DIM + qf * 4]) = acc;
}

// ---------------- 2. q_T and sigmoid(o_T) from last xp row ------------------
__global__ void qo_kernel(const float* __restrict__ Wq, const float* __restrict__ bq,
                          const float* __restrict__ Wo, const float* __restrict__ bo) {
    int warp = threadIdx.x >> 5, lane = threadIdx.x & 31;
    int b = blockIdx.x * 8 + warp;
    if (b >= H_DIM) return;
    const float* W  = blockIdx.y ? Wo : Wq;
    const float* bb = blockIdx.y ? bo : bq;
    const float* xr = &g_xp[(TP - 1) * F_DIM];
    float s = 0.f;
    for (int f = lane; f < F_DIM; f += 32) s = fmaf(W[b * F_DIM + f], xr[f], s);
#pragma unroll
    for (int off = 16; off; off >>= 1) s += __shfl_xor_sync(0xffffffffu, s, off);
    if (lane == 0) {
        float z = s + bb[b];
        if (blockIdx.y) g_oT[b] = 1.f / (1.f + expf(-z));
        else            g_qT[b] = z;
    }
}

// ---------------- 3. f32x2 GEMM: xp(2051x256) @ W^T for k,v,i,f -------------
// Tiles: BM=128 x BN=96 -> grid 17 x 16 = 272 CTAs = single wave at occ 2.
#define BM 128
#define BN 96
#define BK 16
#define AS_S (BM + 2)   // 130
#define BS_S (BN + 4)   // 100
#define NKT  (F_DIM / BK)

__global__ __launch_bounds__(256, 2)
void proj_gemm(const float* __restrict__ Wk, const float* __restrict__ bk,
               const float* __restrict__ Wv, const float* __restrict__ bv,
               const float* __restrict__ Wi, const float* __restrict__ bi,
               const float* __restrict__ Wf, const float* __restrict__ bf) {
    __shared__ float As[2][BK][AS_S];
    __shared__ float Bs[2][BK][BS_S];

    const int proj = blockIdx.y >> 2;            // 4 n-tiles per projection
    const int n0p  = (blockIdx.y & 3) * BN;      // col base within projection
    const int t0   = blockIdx.x * BM;
    const int tid  = threadIdx.x;
    const int tn   = tid & 15;                    // 16 groups x 6 cols
    const int tm   = tid >> 4;                    // 16 groups x 8 rows

    const float* W; const float* bias; float* out;
    switch (proj) {
        case 0: W = Wk; bias = bk; out = g_k;  break;
        case 1: W = Wv; bias = bv; out = g_v;  break;
        case 2: W = Wi; bias = bi; out = g_zi; break;
        default:W = Wf; bias = bf; out = g_lf; break;
    }
    const float* Wb = W + (size_t)n0p * F_DIM;    // 96 rows of this tile

    float4 pA[2];
    float2 pB[3];

    ull acc[4][6];
#pragma unroll
    for (int i = 0; i < 4; ++i)
#pragma unroll
        for (int j = 0; j < 6; ++j) acc[i][j] = 0ull;

    // --- prologue: load k-tile 0 ---
#pragma unroll
    for (int i = 0; i < 2; ++i) {
        int idx = tid + i * 256, row = idx >> 2, q = idx & 3;
        int tt = t0 + row;
        pA[i] = (tt < TP) ? *reinterpret_cast<const float4*>(&g_xp[tt * F_DIM + q * 4])
                          : make_float4(0.f, 0.f, 0.f, 0.f);
    }
#pragma unroll
    for (int i = 0; i < 3; ++i) {
        int idx = tid + i * 256, row = idx >> 3, p = idx & 7;
        pB[i] = *reinterpret_cast<const float2*>(&Wb[row * F_DIM + p * 2]);
    }
    // store to buffer 0
#pragma unroll
    for (int i = 0; i < 2; ++i) {
        int idx = tid + i * 256, row = idx >> 2, q = idx & 3;
        As[0][q * 4 + 0][row] = pA[i].x; As[0][q * 4 + 1][row] = pA[i].y;
        As[0][q * 4 + 2][row] = pA[i].z; As[0][q * 4 + 3][row] = pA[i].w;
    }
#pragma unroll
    for (int i = 0; i < 3; ++i) {
        int idx = tid + i * 256, row = idx >> 3, p = idx & 7;
        Bs[0][p * 2 + 0][row] = pB[i].x; Bs[0][p * 2 + 1][row] = pB[i].y;
    }
    __syncthreads();

    for (int kt = 0; kt < NKT; ++kt) {
        const int buf = kt & 1;
        const int k0n = (kt + 1) * BK;
        if (kt + 1 < NKT) {
#pragma unroll
            for (int i = 0; i < 2; ++i) {
                int idx = tid + i * 256, row = idx >> 2, q = idx & 3;
                int tt = t0 + row;
                pA[i] = (tt < TP) ? *reinterpret_cast<const float4*>(&g_xp[tt * F_DIM + k0n + q * 4])
                                  : make_float4(0.f, 0.f, 0.f, 0.f);
            }
#pragma unroll
            for (int i = 0; i < 3; ++i) {
                int idx = tid + i * 256, row = idx >> 3, p = idx & 7;
                pB[i] = *reinterpret_cast<const float2*>(&Wb[row * F_DIM + k0n + p * 2]);
            }
        }
#pragma unroll
        for (int kk = 0; kk < BK; ++kk) {
            const ull* a8 = reinterpret_cast<const ull*>(&As[buf][kk][tm * 8]);
            ull a0 = a8[0], a1 = a8[1], a2 = a8[2], a3 = a8[3];
            const float2* bp = reinterpret_cast<const float2*>(&Bs[buf][kk][tn * 6]);
            float2 b01 = bp[0], b23 = bp[1], b45 = bp[2];
            ull bb[6];
            bb[0] = pack2(b01.x); bb[1] = pack2(b01.y);
            bb[2] = pack2(b23.x); bb[3] = pack2(b23.y);
            bb[4] = pack2(b45.x); bb[5] = pack2(b45.y);
#pragma unroll
            for (int j = 0; j < 6; ++j) {
                fma2(acc[0][j], a0, bb[j]);
                fma2(acc[1][j], a1, bb[j]);
                fma2(acc[2][j], a2, bb[j]);
                fma2(acc[3][j], a3, bb[j]);
            }
        }
        if (kt + 1 < NKT) {
            const int nb = buf ^ 1;
#pragma unroll
            for (int i = 0; i < 2; ++i) {
                int idx = tid + i * 256, row = idx >> 2, q = idx & 3;
                As[nb][q * 4 + 0][row] = pA[i].x; As[nb][q * 4 + 1][row] = pA[i].y;
                As[nb][q * 4 + 2][row] = pA[i].z; As[nb][q * 4 + 3][row] = pA[i].w;
            }
#pragma unroll
            for (int i = 0; i < 3; ++i) {
                int idx = tid + i * 256, row = idx >> 3, p = idx & 7;
                Bs[nb][p * 2 + 0][row] = pB[i].x; Bs[nb][p * 2 + 1][row] = pB[i].y;
            }
        }
        __syncthreads();
    }

    // Epilogue: per column, 8 contiguous t values -> 2x float4 stores
    const int tbase = t0 + tm * 8;
#pragma unroll
    for (int n = 0; n < 6; ++n) {
        int col = n0p + tn * 6 + n;               // column within projection
        float bias_n = bias[col];
        float vals[8];
#pragma unroll
        for (int mp = 0; mp < 4; ++mp)
            unpack2(acc[mp][n], vals[2 * mp], vals[2 * mp + 1]);
#pragma unroll
        for (int e = 0; e < 8; ++e) {
            float z = vals[e] + bias_n;
            if (proj == 0)      vals[e] = z * INV_SQRT_H;
            else if (proj == 3) vals[e] = fminf(z, 0.f) - log1pf(__expf(-fabsf(z)));
            else                vals[e] = z;
        }
        float* op = out + (size_t)col * TPAD + tbase;
        if (tbase + 7 < TP) {
            *reinterpret_cast<float4*>(op)     = make_float4(vals[0], vals[1], vals[2], vals[3]);
            *reinterpret_cast<float4*>(op + 4) = make_float4(vals[4], vals[5], vals[6], vals[7]);
        } else {
#pragma unroll
            for (int e = 0; e < 8; ++e)
                if (tbase + e < TP) op[e] = vals[e];
        }
    }
}

// ---------------- 4. per-channel suffix scan; skip dead exp -----------------
__global__ __launch_bounds__(256)
void scan_kernel() {
    const int b = blockIdx.x;
    const int tid = threadIdx.x;
    const int CH = 9;                       // ceil(2051/256)
    const float* lf = &g_lf[b * TPAD];
    const float* zi = &g_zi[b * TPAD];
    const float* kk = &g_k [b * TPAD];
    const float qb  = g_qT[b];
    float* co = &g_contrib[b * TPAD];

    int lo = tid * CH;
    int hi = min(lo + CH, TP);

    float s = 0.f;
    for (int t = lo; t < hi; ++t) s += lf[t];

    __shared__ float sfx[256];
    __shared__ int   smin[256];
    sfx[tid] = s;
    __syncthreads();
#pragma unroll
    for (int d = 1; d < 256; d <<= 1) {
        float add = (tid + d < 256) ? sfx[tid + d] : 0.f;
        __syncthreads();
        sfx[tid] += add;
        __syncthreads();
    }
    float run = (tid + 1 < 256) ? sfx[tid + 1] : 0.f;  // suffix sum of later chunks
    int live_min = TP;
    for (int t = hi - 1; t >= lo; --t) {
        float zr = zi[t] + run;
        float c = 0.f;
        if (zr > -80.f) {                   // exp(zr) < 1.8e-35 otherwise: dead
            c = __expf(zr) * kk[t] * qb;
            live_min = t;
        }
        co[t] = c;
        run += lf[t];
    }
    smin[tid] = live_min;
    __syncthreads();
#pragma unroll
    for (int d = 128; d; d >>= 1) {
        if (tid < d) smin[tid] = min(smin[tid], smin[tid + d]);
        __syncthreads();
    }
    if (tid == 0) atomicMin(&g_tmin, smin[0]);
}

// ---------------- 5. reduce over b -> w (skip dead prefix) ------------------
__global__ void reduce_w_fused() {
    int t = blockIdx.x * blockDim.x + threadIdx.x;
    if (t >= TP) return;
    if (t < g_tmin) { g_w[t] = 0.f; return; }
    float s = 0.f;
#pragma unroll 8
    for (int b = 0; b < H_DIM; ++b) s += g_contrib[b * TPAD + t];
    g_w[t] = s;
}

// ---------------- 6. final: h[a] = o[a] * (v_a . w) / max(|sum w|,1) ---------
__global__ __launch_bounds__(256)
void final_kernel(float* __restrict__ out) {
    const int a = blockIdx.x;
    const int tid = threadIdx.x;
    const float4* v4 = reinterpret_cast<const float4*>(&g_v[a * TPAD]);
    const float4* w4 = reinterpret_cast<const float4*>(g_w);
    const int NV = TP / 4;                 // 512 full float4 -> [0, 2048)
    const int i0 = (g_tmin & ~3) >> 2;     // skip dead prefix (w==0 there)
    float num = 0.f, den = 0.f;
    for (int i = i0 + tid; i < NV; i += 256) {
        float4 v = v4[i], w = w4[i];
        num = fmaf(v.x, w.x, num); den += w.x;
        num = fmaf(v.y, w.y, num); den += w.y;
        num = fmaf(v.z, w.z, num); den += w.z;
        num = fmaf(v.w, w.w, num); den += w.w;
    }
    if (tid < TP - NV * 4) {               // tail 2048..2050
        int t = NV * 4 + tid;
        float wt = g_w[t];
        num = fmaf(g_v[a * TPAD + t], wt, num);
        den += wt;
    }
    __shared__ float sn[256], sd[256];
    sn[tid] = num; sd[tid] = den;
    __syncthreads();
#pragma unroll
    for (int s = 128; s; s >>= 1) {
        if (tid < s) { sn[tid] += sn[tid + s]; sd[tid] += sd[tid + s]; }
        __syncthreads();
    }
    if (tid == 0) {
        float dd = fmaxf(fabsf(sd[0]), 1.0f);
        out[a] = g_oT[a] * sn[0] / dd;
    }
}

// -----------------------------------------------------------------------------
extern "C" void kernel_launch(void* const* d_in, const int* in_sizes, int n_in,
                              void* d_out, int out_size) {
    const float* x  = (const float*)d_in[0];
    const float* Wq = (const float*)d_in[1];  const float* bq = (const float*)d_in[2];
    const float* Wk = (const float*)d_in[3];  const float* bk = (const float*)d_in[4];
    const float* Wv = (const float*)d_in[5];  const float* bv = (const float*)d_in[6];
    const float* Wi = (const float*)d_in[7];  const float* bi = (const float*)d_in[8];
    const float* Wf = (const float*)d_in[9];  const float* bf = (const float*)d_in[10];
    const float* Wo = (const float*)d_in[11]; const float* bo = (const float*)d_in[12];
    const float* cw = (const float*)d_in[13]; const float* cb = (const float*)d_in[14];
    float* out = (float*)d_out;

    conv_kernel<<<(TP * (F_DIM / 4) + 255) / 256, 256>>>(x, cw, cb);
    qo_kernel<<<dim3(48, 2), 256>>>(Wq, bq, Wo, bo);
    proj_gemm<<<dim3((TP + BM - 1) / BM, 16), 256>>>(Wk, bk, Wv, bv, Wi, bi, Wf, bf);
    scan_kernel<<<H_DIM, 256>>>();
    reduce_w_fused<<<(TP + 255) / 256, 256>>>();
    final_kernel<<<H_DIM, 256>>>(out);
}